// round 1
// baseline (speedup 1.0000x reference)
#include <cuda_runtime.h>
#include <cstdint>

// Problem constants (fixed shapes per reference)
#define EE      800000
#define NNODES  100000
#define DD      256
#define NREL    16
#define NBASES  8
#define TILE_M  128
#define PAD_E   (EE + NREL * TILE_M)      // 802048
#define NTILES  (PAD_E / TILE_M)          // 6266

// ---------------- scratch (device globals; no allocation allowed) ----------------
__device__ float g_W[NREL * DD * DD];     // per-relation weights, tf32-rounded (4 MB)
__device__ int   g_hist[NREL];
__device__ int   g_offpad[NREL + 1];      // padded segment offsets (multiples of 128)
__device__ int   g_cursor[NREL];
__device__ int   g_srcrow[PAD_E];         // node_ids[src[e]] after sort
__device__ int   g_dstn[PAD_E];           // dst after sort (-1 = padding)
__device__ float g_normv[PAD_E];          // norm after sort (0 = padding)
__device__ int   g_cnt[NNODES];

// ---------------- helpers ----------------
__device__ __forceinline__ unsigned f2tf32(float x) {
    unsigned u;
    asm volatile("cvt.rna.tf32.f32 %0, %1;\n" : "=r"(u) : "f"(x));
    return u;
}

__device__ __forceinline__ void mma_tf32(float c[4], const unsigned a[4],
                                         unsigned b0, unsigned b1) {
    asm volatile(
        "mma.sync.aligned.m16n8k8.row.col.f32.tf32.tf32.f32 "
        "{%0,%1,%2,%3}, {%4,%5,%6,%7}, {%8,%9}, {%0,%1,%2,%3};\n"
        : "+f"(c[0]), "+f"(c[1]), "+f"(c[2]), "+f"(c[3])
        : "r"(a[0]), "r"(a[1]), "r"(a[2]), "r"(a[3]), "r"(b0), "r"(b1));
}

// ---------------- K0: zero/reset everything ----------------
__global__ void k_init(float* __restrict__ out) {
    int i = blockIdx.x * blockDim.x + threadIdx.x;
    int stride = gridDim.x * blockDim.x;
    for (int j = i; j < NNODES * DD; j += stride) out[j] = 0.0f;
    for (int j = i; j < PAD_E; j += stride) {
        g_dstn[j] = -1; g_normv[j] = 0.0f; g_srcrow[j] = 0;
    }
    for (int j = i; j < NNODES; j += stride) g_cnt[j] = 0;
    if (i < NREL) g_hist[i] = 0;
}

// ---------------- K1: W[r] = sum_b w_comp[r,b] * basis[b], tf32-rounded ----------------
__global__ void k_w(const float* __restrict__ basis, const float* __restrict__ wcomp) {
    int idx = blockIdx.x * blockDim.x + threadIdx.x;
    if (idx >= NREL * DD * DD) return;
    int r   = idx >> 16;       // / (256*256)
    int rem = idx & 65535;
    float s = 0.0f;
#pragma unroll
    for (int b = 0; b < NBASES; b++)
        s = fmaf(wcomp[r * NBASES + b], basis[b * (DD * DD) + rem], s);
    g_W[idx] = __uint_as_float(f2tf32(s));
}

// ---------------- K2: histogram by relation + in-degree counts ----------------
__global__ void k_hist(const int* __restrict__ et, const int* __restrict__ dst) {
    __shared__ int h[NREL];
    if (threadIdx.x < NREL) h[threadIdx.x] = 0;
    __syncthreads();
    int e = blockIdx.x * blockDim.x + threadIdx.x;
    if (e < EE) {
        atomicAdd(&h[et[e]], 1);
        atomicAdd(&g_cnt[dst[e]], 1);
    }
    __syncthreads();
    if (threadIdx.x < NREL) atomicAdd(&g_hist[threadIdx.x], h[threadIdx.x]);
}

// ---------------- K3: tiny prefix scan (padded to 128) ----------------
__global__ void k_scan() {
    if (threadIdx.x == 0 && blockIdx.x == 0) {
        int acc = 0;
        for (int r = 0; r < NREL; r++) {
            g_offpad[r] = acc;
            g_cursor[r] = acc;
            acc += ((g_hist[r] + TILE_M - 1) / TILE_M) * TILE_M;
        }
        g_offpad[NREL] = acc;
    }
}

// ---------------- K4: counting-sort scatter by relation (warp-aggregated) -----------
__global__ void k_scatter(const int* __restrict__ nid, const int* __restrict__ src,
                          const int* __restrict__ dst, const int* __restrict__ et,
                          const float* __restrict__ norm) {
    int e = blockIdx.x * blockDim.x + threadIdx.x;
    if (e >= EE) return;  // EE divisible by 256: whole warps stay converged
    int t = et[e];
    int lane = threadIdx.x & 31;
    unsigned mask = __match_any_sync(0xffffffffu, t);
    int leader = __ffs(mask) - 1;
    int base;
    if (lane == leader) base = atomicAdd(&g_cursor[t], __popc(mask));
    base = __shfl_sync(mask, base, leader);
    int pos = base + __popc(mask & ((1u << lane) - 1u));
    g_srcrow[pos] = nid[src[e]];
    g_dstn[pos]   = dst[e];
    g_normv[pos]  = norm[e];
}

// ---------------- K5: grouped GEMM (tf32 mma) + atomic scatter to out -------------
// grid = (NTILES, 2): blockIdx.x = 128-edge tile (uniform relation after padding),
// blockIdx.y = which 128-wide half of the 256 output columns.
__global__ void __launch_bounds__(256) k_gemm(const float* __restrict__ emb,
                                              float* __restrict__ out) {
    __shared__ float sA[TILE_M * 32];   // swizzled A tile (tf32-rounded, norm-scaled)
    __shared__ float sB[32 * 128];      // swizzled W tile
    __shared__ int   sdst[TILE_M];
    __shared__ int   ssrc[TILE_M];
    __shared__ float snorm[TILE_M];

    int row0 = blockIdx.x * TILE_M;
    if (row0 >= g_offpad[NREL]) return;
    int r = 0;
#pragma unroll
    for (int i = 1; i < NREL; i++) r += (g_offpad[i] <= row0) ? 1 : 0;

    int tid = threadIdx.x;
    if (tid < TILE_M) {
        sdst[tid]  = g_dstn[row0 + tid];
        ssrc[tid]  = g_srcrow[row0 + tid];
        snorm[tid] = g_normv[row0 + tid];
    }
    __syncthreads();

    const float* Wr = g_W + r * (DD * DD) + blockIdx.y * 128;

    int lane = tid & 31;
    int warp = tid >> 5;
    int wm = (warp & 3) * 32;   // 4 warps over M
    int wn = (warp >> 2) * 64;  // 2 warps over N (within the 128 half)
    int qr = lane >> 2, qc = lane & 3;

    float acc[2][8][4];
#pragma unroll
    for (int mt = 0; mt < 2; mt++)
#pragma unroll
        for (int nt = 0; nt < 8; nt++)
#pragma unroll
            for (int k = 0; k < 4; k++) acc[mt][nt][k] = 0.0f;

    for (int k0 = 0; k0 < DD; k0 += 32) {
        // --- load A tile: gather 128 emb rows (L2-resident), scale by norm, tf32-round
#pragma unroll
        for (int v = tid; v < 1024; v += 256) {
            int row = v >> 3;
            int c4  = (v & 7) << 2;
            const float4 x4 = *reinterpret_cast<const float4*>(
                emb + (long)ssrc[row] * DD + k0 + c4);
            float nm = snorm[row];
            int base = row * 32 + (c4 ^ ((row & 7) << 2));
            float4 o;
            o.x = __uint_as_float(f2tf32(x4.x * nm));
            o.y = __uint_as_float(f2tf32(x4.y * nm));
            o.z = __uint_as_float(f2tf32(x4.z * nm));
            o.w = __uint_as_float(f2tf32(x4.w * nm));
            *reinterpret_cast<float4*>(&sA[base]) = o;
        }
        // --- load B tile: W[r] rows k0..k0+31, 128 cols (already tf32-rounded)
#pragma unroll
        for (int v = tid; v < 1024; v += 256) {
            int k  = v >> 5;
            int j4 = (v & 31) << 2;
            float4 w4 = *reinterpret_cast<const float4*>(Wr + (long)(k0 + k) * DD + j4);
            int base = k * 128 + (j4 ^ ((k & 3) << 3));
            *reinterpret_cast<float4*>(&sB[base]) = w4;
        }
        __syncthreads();

#pragma unroll
        for (int ks = 0; ks < 32; ks += 8) {
            unsigned af[2][4];
#pragma unroll
            for (int mt = 0; mt < 2; mt++) {
                int rlo = wm + mt * 16 + qr;
                int rhi = rlo + 8;
                int sw  = (rlo & 7) << 2;        // rhi & 7 == rlo & 7
                af[mt][0] = __float_as_uint(sA[rlo * 32 + ((ks + qc)     ^ sw)]);
                af[mt][1] = __float_as_uint(sA[rhi * 32 + ((ks + qc)     ^ sw)]);
                af[mt][2] = __float_as_uint(sA[rlo * 32 + ((ks + 4 + qc) ^ sw)]);
                af[mt][3] = __float_as_uint(sA[rhi * 32 + ((ks + 4 + qc) ^ sw)]);
            }
            int swb = qc << 3;
#pragma unroll
            for (int nt = 0; nt < 8; nt++) {
                int col = wn + nt * 8 + qr;
                unsigned b0 = __float_as_uint(sB[(ks + qc)     * 128 + (col ^ swb)]);
                unsigned b1 = __float_as_uint(sB[(ks + 4 + qc) * 128 + (col ^ swb)]);
                mma_tf32(acc[0][nt], af[0], b0, b1);
                mma_tf32(acc[1][nt], af[1], b0, b1);
            }
        }
        __syncthreads();
    }

    // --- epilogue: atomic scatter rows into out[dst]
    int colbase = blockIdx.y * 128 + wn;
#pragma unroll
    for (int mt = 0; mt < 2; mt++) {
        int rlo = wm + mt * 16 + qr;
        int d0 = sdst[rlo];
        int d1 = sdst[rlo + 8];
#pragma unroll
        for (int nt = 0; nt < 8; nt++) {
            int col = colbase + nt * 8 + qc * 2;
            if (d0 >= 0) {
                atomicAdd(out + (long)d0 * DD + col,     acc[mt][nt][0]);
                atomicAdd(out + (long)d0 * DD + col + 1, acc[mt][nt][1]);
            }
            if (d1 >= 0) {
                atomicAdd(out + (long)d1 * DD + col,     acc[mt][nt][2]);
                atomicAdd(out + (long)d1 * DD + col + 1, acc[mt][nt][3]);
            }
        }
    }
}

// ---------------- K6: mean + bias ----------------
__global__ void k_final(float* __restrict__ out, const float* __restrict__ hbias) {
    int i = blockIdx.x * blockDim.x + threadIdx.x;
    if (i >= NNODES * DD) return;
    int n = i >> 8;
    int c = i & 255;
    float cnt = (float)g_cnt[n];
    float v = out[i];
    v = (cnt > 0.0f) ? v / cnt : 0.0f;
    out[i] = v + hbias[c];
}

// ---------------- launch ----------------
extern "C" void kernel_launch(void* const* d_in, const int* in_sizes, int n_in,
                              void* d_out, int out_size) {
    const int*   node_ids = (const int*)  d_in[0];
    const int*   src      = (const int*)  d_in[1];
    const int*   dst      = (const int*)  d_in[2];
    const int*   etypes   = (const int*)  d_in[3];
    const float* norm     = (const float*)d_in[4];
    const float* emb      = (const float*)d_in[5];
    const float* basis    = (const float*)d_in[6];
    const float* wcomp    = (const float*)d_in[7];
    const float* hbias    = (const float*)d_in[8];
    float* out = (float*)d_out;

    k_init<<<2048, 256>>>(out);
    k_w<<<(NREL * DD * DD + 255) / 256, 256>>>(basis, wcomp);
    k_hist<<<(EE + 255) / 256, 256>>>(etypes, dst);
    k_scan<<<1, 32>>>();
    k_scatter<<<(EE + 255) / 256, 256>>>(node_ids, src, dst, etypes, norm);
    dim3 g(NTILES, 2);
    k_gemm<<<g, 256>>>(emb, out);
    k_final<<<(NNODES * DD + 255) / 256, 256>>>(out, hbias);
}

// round 2
// speedup vs baseline: 1.4341x; 1.4341x over previous
#include <cuda_runtime.h>
#include <cstdint>

// Problem constants (fixed shapes per reference)
#define EE      800000
#define NNODES  100000
#define DD      256
#define NREL    16
#define NBASES  8
#define TILE_M  128
#define PAD_E   (EE + NREL * TILE_M)      // 802048
#define NTILES  (PAD_E / TILE_M)          // 6266

// ---------------- scratch (device globals; no allocation allowed) ----------------
__device__ float g_W[NREL * DD * DD];       // per-relation weights, tf32-rounded (4 MB)
__device__ float g_embtf[NNODES * DD];      // tf32-rounded embedding copy (100 MB)
__device__ int   g_hist[NREL];
__device__ int   g_offpad[NREL + 1];
__device__ int   g_cursor[NREL];
__device__ int   g_srcrow[PAD_E];
__device__ int   g_dstn[PAD_E];
__device__ float g_normv[PAD_E];
__device__ int   g_cnt[NNODES];

// ---------------- helpers ----------------
__device__ __forceinline__ unsigned f2tf32(float x) {
    unsigned u;
    asm volatile("cvt.rna.tf32.f32 %0, %1;\n" : "=r"(u) : "f"(x));
    return u;
}

__device__ __forceinline__ void mma_tf32(float c[4], const unsigned a[4],
                                         unsigned b0, unsigned b1) {
    asm volatile(
        "mma.sync.aligned.m16n8k8.row.col.f32.tf32.tf32.f32 "
        "{%0,%1,%2,%3}, {%4,%5,%6,%7}, {%8,%9}, {%0,%1,%2,%3};\n"
        : "+f"(c[0]), "+f"(c[1]), "+f"(c[2]), "+f"(c[3])
        : "r"(a[0]), "r"(a[1]), "r"(a[2]), "r"(a[3]), "r"(b0), "r"(b1));
}

__device__ __forceinline__ void cp16(uint32_t saddr, const void* gaddr) {
    asm volatile("cp.async.cg.shared.global [%0], [%1], 16;\n"
                 :: "r"(saddr), "l"(gaddr));
}
__device__ __forceinline__ void cp_commit() {
    asm volatile("cp.async.commit_group;\n" ::: "memory");
}

__device__ __forceinline__ void red4(float* p, float x, float y, float z, float w) {
    asm volatile("red.global.add.v4.f32 [%0], {%1,%2,%3,%4};\n"
                 :: "l"(p), "f"(x), "f"(y), "f"(z), "f"(w) : "memory");
}

// ---------------- K0: zero/reset everything ----------------
__global__ void k_init(float* __restrict__ out) {
    int i = blockIdx.x * blockDim.x + threadIdx.x;
    int stride = gridDim.x * blockDim.x;
    for (int j = i; j < NNODES * DD; j += stride) out[j] = 0.0f;
    for (int j = i; j < PAD_E; j += stride) {
        g_dstn[j] = -1; g_normv[j] = 0.0f; g_srcrow[j] = 0;
    }
    for (int j = i; j < NNODES; j += stride) g_cnt[j] = 0;
    if (i < NREL) g_hist[i] = 0;
}

// ---------------- K1: W[r] = sum_b w_comp[r,b] * basis[b], tf32-rounded -----------
__global__ void k_w(const float* __restrict__ basis, const float* __restrict__ wcomp) {
    int idx = blockIdx.x * blockDim.x + threadIdx.x;
    if (idx >= NREL * DD * DD) return;
    int r   = idx >> 16;
    int rem = idx & 65535;
    float s = 0.0f;
#pragma unroll
    for (int b = 0; b < NBASES; b++)
        s = fmaf(wcomp[r * NBASES + b], basis[b * (DD * DD) + rem], s);
    g_W[idx] = __uint_as_float(f2tf32(s));
}

// ---------------- K1b: tf32-round the embedding table once --------------------------
__global__ void k_round(const float* __restrict__ emb) {
    int i = blockIdx.x * blockDim.x + threadIdx.x;
    int stride = gridDim.x * blockDim.x;
    for (int j = i; j < (NNODES * DD) / 4; j += stride) {
        float4 v = reinterpret_cast<const float4*>(emb)[j];
        float4 o;
        o.x = __uint_as_float(f2tf32(v.x));
        o.y = __uint_as_float(f2tf32(v.y));
        o.z = __uint_as_float(f2tf32(v.z));
        o.w = __uint_as_float(f2tf32(v.w));
        reinterpret_cast<float4*>(g_embtf)[j] = o;
    }
}

// ---------------- K2: histogram by relation + in-degree counts ----------------
__global__ void k_hist(const int* __restrict__ et, const int* __restrict__ dst) {
    __shared__ int h[NREL];
    if (threadIdx.x < NREL) h[threadIdx.x] = 0;
    __syncthreads();
    int e = blockIdx.x * blockDim.x + threadIdx.x;
    if (e < EE) {
        atomicAdd(&h[et[e]], 1);
        atomicAdd(&g_cnt[dst[e]], 1);
    }
    __syncthreads();
    if (threadIdx.x < NREL) atomicAdd(&g_hist[threadIdx.x], h[threadIdx.x]);
}

// ---------------- K3: tiny prefix scan (padded to 128) ----------------
__global__ void k_scan() {
    if (threadIdx.x == 0 && blockIdx.x == 0) {
        int acc = 0;
        for (int r = 0; r < NREL; r++) {
            g_offpad[r] = acc;
            g_cursor[r] = acc;
            acc += ((g_hist[r] + TILE_M - 1) / TILE_M) * TILE_M;
        }
        g_offpad[NREL] = acc;
    }
}

// ---------------- K4: counting-sort scatter by relation (warp-aggregated) ---------
__global__ void k_scatter(const int* __restrict__ nid, const int* __restrict__ src,
                          const int* __restrict__ dst, const int* __restrict__ et,
                          const float* __restrict__ norm) {
    int e = blockIdx.x * blockDim.x + threadIdx.x;
    if (e >= EE) return;  // EE divisible by 256: whole warps stay converged
    int t = et[e];
    int lane = threadIdx.x & 31;
    unsigned mask = __match_any_sync(0xffffffffu, t);
    int leader = __ffs(mask) - 1;
    int base;
    if (lane == leader) base = atomicAdd(&g_cursor[t], __popc(mask));
    base = __shfl_sync(mask, base, leader);
    int pos = base + __popc(mask & ((1u << lane) - 1u));
    g_srcrow[pos] = nid[src[e]];
    g_dstn[pos]   = dst[e];
    g_normv[pos]  = norm[e];
}

// ---------------- K5: grouped GEMM (tf32 mma), cp.async double-buffered ----------
// Dynamic smem: sA[2][128*32] | sB[2][32*128]  (65536 B). After the mainloop the
// whole 64 KB region is reused as a 128x128 staging tile for the v4 red epilogue.
// grid = (NTILES, 2): x = 128-edge tile (uniform relation after padding),
// y = which 128-wide half of the 256 output columns.
__global__ void __launch_bounds__(256) k_gemm(float* __restrict__ out) {
    extern __shared__ float smemf[];
    float* sA = smemf;            // 2 * 4096 floats
    float* sB = smemf + 8192;     // 2 * 4096 floats
    __shared__ int   sdst[TILE_M];
    __shared__ int   ssrc[TILE_M];
    __shared__ float snorm[TILE_M];

    int row0 = blockIdx.x * TILE_M;
    if (row0 >= g_offpad[NREL]) return;
    int r = 0;
#pragma unroll
    for (int i = 1; i < NREL; i++) r += (g_offpad[i] <= row0) ? 1 : 0;

    int tid = threadIdx.x;
    if (tid < TILE_M) {
        sdst[tid]  = g_dstn[row0 + tid];
        ssrc[tid]  = g_srcrow[row0 + tid];
        snorm[tid] = g_normv[row0 + tid];
    }
    __syncthreads();

    const float* Wr = g_W + r * (DD * DD) + blockIdx.y * 128;
    uint32_t sA_u = (uint32_t)__cvta_generic_to_shared(sA);
    uint32_t sB_u = (uint32_t)__cvta_generic_to_shared(sB);

    // async stage loaders: stage `it` covers K columns [it*32, it*32+32)
    auto loadA = [&](int it, int buf) {
#pragma unroll
        for (int v = tid; v < 1024; v += 256) {
            int row = v >> 3;
            int c4  = (v & 7) << 2;
            const float* g = g_embtf + (long)ssrc[row] * DD + it * 32 + c4;
            uint32_t s = sA_u + 4u * (buf * 4096 + row * 32 + (c4 ^ ((row & 7) << 2)));
            cp16(s, g);
        }
    };
    auto loadB = [&](int it, int buf) {
#pragma unroll
        for (int v = tid; v < 1024; v += 256) {
            int k  = v >> 5;
            int j4 = (v & 31) << 2;
            const float* g = Wr + (long)(it * 32 + k) * DD + j4;
            uint32_t s = sB_u + 4u * (buf * 4096 + k * 128 + (j4 ^ ((k & 3) << 3)));
            cp16(s, g);
        }
    };

    int lane = tid & 31;
    int warp = tid >> 5;
    int wm = (warp & 3) * 32;   // 4 warps over M
    int wn = (warp >> 2) * 64;  // 2 warps over N (within the 128 half)
    int qr = lane >> 2, qc = lane & 3;

    float acc[2][8][4];
#pragma unroll
    for (int mt = 0; mt < 2; mt++)
#pragma unroll
        for (int nt = 0; nt < 8; nt++)
#pragma unroll
            for (int k = 0; k < 4; k++) acc[mt][nt][k] = 0.0f;

    loadA(0, 0);
    loadB(0, 0);
    cp_commit();

#pragma unroll 1
    for (int it = 0; it < 8; it++) {
        if (it < 7) {
            loadA(it + 1, (it + 1) & 1);
            loadB(it + 1, (it + 1) & 1);
            cp_commit();
            asm volatile("cp.async.wait_group 1;\n" ::: "memory");
        } else {
            asm volatile("cp.async.wait_group 0;\n" ::: "memory");
        }
        __syncthreads();

        const float* cA = sA + (it & 1) * 4096;
        const float* cB = sB + (it & 1) * 4096;
#pragma unroll
        for (int ks = 0; ks < 32; ks += 8) {
            unsigned af[2][4];
#pragma unroll
            for (int mt = 0; mt < 2; mt++) {
                int rlo = wm + mt * 16 + qr;
                int rhi = rlo + 8;
                int sw  = (rlo & 7) << 2;
                af[mt][0] = __float_as_uint(cA[rlo * 32 + ((ks + qc)     ^ sw)]);
                af[mt][1] = __float_as_uint(cA[rhi * 32 + ((ks + qc)     ^ sw)]);
                af[mt][2] = __float_as_uint(cA[rlo * 32 + ((ks + 4 + qc) ^ sw)]);
                af[mt][3] = __float_as_uint(cA[rhi * 32 + ((ks + 4 + qc) ^ sw)]);
            }
            int swb = qc << 3;
#pragma unroll
            for (int nt = 0; nt < 8; nt++) {
                int col = wn + nt * 8 + qr;
                unsigned b0 = __float_as_uint(cB[(ks + qc)     * 128 + (col ^ swb)]);
                unsigned b1 = __float_as_uint(cB[(ks + 4 + qc) * 128 + (col ^ swb)]);
                mma_tf32(acc[0][nt], af[0], b0, b1);
                mma_tf32(acc[1][nt], af[1], b0, b1);
            }
        }
        __syncthreads();
    }

    // --- epilogue: scale by per-edge norm, stage 128x128 tile in smem (swizzled),
    //     then 16-byte vector reductions into out[dst].
    float* sT = smemf;  // 16384 floats = 128 x 128
#pragma unroll
    for (int mt = 0; mt < 2; mt++) {
        int rlo = wm + mt * 16 + qr;
        int rhi = rlo + 8;
        float n0 = snorm[rlo];
        float n1 = snorm[rhi];
        int sw = (rlo & 7) << 2;   // rhi & 7 == rlo & 7
#pragma unroll
        for (int nt = 0; nt < 8; nt++) {
            int col = wn + nt * 8 + qc * 2;
            float2 lo = make_float2(acc[mt][nt][0] * n0, acc[mt][nt][1] * n0);
            float2 hi = make_float2(acc[mt][nt][2] * n1, acc[mt][nt][3] * n1);
            *reinterpret_cast<float2*>(&sT[rlo * 128 + (col ^ sw)]) = lo;
            *reinterpret_cast<float2*>(&sT[rhi * 128 + (col ^ sw)]) = hi;
        }
    }
    __syncthreads();

    int colbase = blockIdx.y * 128;
#pragma unroll
    for (int v = tid; v < 4096; v += 256) {
        int row = v >> 5;
        int c4  = (v & 31) << 2;
        int d = sdst[row];
        if (d < 0) continue;
        int sw = (row & 7) << 2;
        float4 val = *reinterpret_cast<float4*>(&sT[row * 128 + (c4 ^ sw)]);
        red4(out + (long)d * DD + colbase + c4, val.x, val.y, val.z, val.w);
    }
}

// ---------------- K6: mean + bias ----------------
__global__ void k_final(float* __restrict__ out, const float* __restrict__ hbias) {
    int i = blockIdx.x * blockDim.x + threadIdx.x;
    if (i >= NNODES * DD) return;
    int n = i >> 8;
    int c = i & 255;
    float cnt = (float)g_cnt[n];
    float v = out[i];
    v = (cnt > 0.0f) ? v / cnt : 0.0f;
    out[i] = v + hbias[c];
}

// ---------------- launch ----------------
extern "C" void kernel_launch(void* const* d_in, const int* in_sizes, int n_in,
                              void* d_out, int out_size) {
    const int*   node_ids = (const int*)  d_in[0];
    const int*   src      = (const int*)  d_in[1];
    const int*   dst      = (const int*)  d_in[2];
    const int*   etypes   = (const int*)  d_in[3];
    const float* norm     = (const float*)d_in[4];
    const float* emb      = (const float*)d_in[5];
    const float* basis    = (const float*)d_in[6];
    const float* wcomp    = (const float*)d_in[7];
    const float* hbias    = (const float*)d_in[8];
    float* out = (float*)d_out;

    static bool attr_set = false;
    if (!attr_set) {
        cudaFuncSetAttribute(k_gemm, cudaFuncAttributeMaxDynamicSharedMemorySize, 65536);
        attr_set = true;
    }

    k_init<<<2048, 256>>>(out);
    k_w<<<(NREL * DD * DD + 255) / 256, 256>>>(basis, wcomp);
    k_round<<<2048, 256>>>(emb);
    k_hist<<<(EE + 255) / 256, 256>>>(etypes, dst);
    k_scan<<<1, 32>>>();
    k_scatter<<<(EE + 255) / 256, 256>>>(node_ids, src, dst, etypes, norm);
    dim3 g(NTILES, 2);
    k_gemm<<<g, 256, 65536>>>(out);
    k_final<<<(NNODES * DD + 255) / 256, 256>>>(out, hbias);
}

// round 5
// speedup vs baseline: 1.6850x; 1.1750x over previous
#include <cuda_runtime.h>
#include <cstdint>

// Problem constants
#define EE      800000
#define NNODES  100000
#define DD      256
#define NREL    16
#define NBASES  8
#define TILE_M  256                       // edges per block
#define PAD_E   (EE + NREL * TILE_M)      // 804096
#define NTILES  (PAD_E / TILE_M)          // 3141

#define STAGE_BYTES 49152                 // A 32KB + B 16KB
#define NSTAGE 4
#define SMEM_BYTES (STAGE_BYTES * NSTAGE) // 196608

// ---------------- scratch (device globals; no allocation allowed) ----------------
__device__ float g_W[NREL * DD * DD];     // per-relation weights [r][k][n], tf32-rounded
__device__ int   g_hist[NREL];
__device__ int   g_offpad[NREL + 1];
__device__ int   g_relcnt[NREL];
__device__ int   g_srcrow[PAD_E];
__device__ int   g_dstn[PAD_E];
__device__ float g_normv[PAD_E];
__device__ int   g_cnt[NNODES];

// ---------------- helpers ----------------
__device__ __forceinline__ unsigned f2tf32(float x) {
    unsigned u;
    asm volatile("cvt.rna.tf32.f32 %0, %1;\n" : "=r"(u) : "f"(x));
    return u;
}
__device__ __forceinline__ void mma_tf32(float c[4], const unsigned a[4],
                                         unsigned b0, unsigned b1) {
    asm volatile(
        "mma.sync.aligned.m16n8k8.row.col.f32.tf32.tf32.f32 "
        "{%0,%1,%2,%3}, {%4,%5,%6,%7}, {%8,%9}, {%0,%1,%2,%3};\n"
        : "+f"(c[0]), "+f"(c[1]), "+f"(c[2]), "+f"(c[3])
        : "r"(a[0]), "r"(a[1]), "r"(a[2]), "r"(a[3]), "r"(b0), "r"(b1));
}
__device__ __forceinline__ void cp16(uint32_t saddr, const void* gaddr) {
    asm volatile("cp.async.cg.shared.global [%0], [%1], 16;\n"
                 :: "r"(saddr), "l"(gaddr));
}
__device__ __forceinline__ void cp_commit() {
    asm volatile("cp.async.commit_group;\n" ::: "memory");
}
__device__ __forceinline__ void red4(float* p, float x, float y, float z, float w) {
    asm volatile("red.global.add.v4.f32 [%0], {%1,%2,%3,%4};\n"
                 :: "l"(p), "f"(x), "f"(y), "f"(z), "f"(w) : "memory");
}

// ---------------- K1: zero everything + W[r] = sum_b w_comp[r,b]*basis[b] --------
__global__ void k_pre(float* __restrict__ out,
                      const float* __restrict__ basis,
                      const float* __restrict__ wcomp) {
    int gi = blockIdx.x * blockDim.x + threadIdx.x;
    int stride = gridDim.x * blockDim.x;
    for (int j = gi; j < NNODES * DD; j += stride) out[j] = 0.0f;
    for (int j = gi; j < PAD_E; j += stride) {
        g_dstn[j] = -1; g_normv[j] = 0.0f; g_srcrow[j] = 0;
    }
    for (int j = gi; j < NNODES; j += stride) g_cnt[j] = 0;
    if (gi < NREL) { g_hist[gi] = 0; g_relcnt[gi] = 0; }

    // W compute: first NREL*256 blocks each do one (r, k-row) of 256 n
    if (blockIdx.x < NREL * DD) {
        int r = blockIdx.x >> 8;
        int k = blockIdx.x & 255;
        float c[NBASES];
#pragma unroll
        for (int b = 0; b < NBASES; b++) c[b] = wcomp[r * NBASES + b];
        int n = threadIdx.x;   // 256 threads = 256 n
        float s = 0.0f;
#pragma unroll
        for (int b = 0; b < NBASES; b++)
            s = fmaf(c[b], basis[b * (DD * DD) + k * DD + n], s);
        g_W[r * (DD * DD) + k * DD + n] = __uint_as_float(f2tf32(s));
    }
}

// ---------------- K2: histogram by relation + in-degree counts ----------------
__global__ void k_hist(const int* __restrict__ et, const int* __restrict__ dst) {
    __shared__ int h[NREL];
    if (threadIdx.x < NREL) h[threadIdx.x] = 0;
    __syncthreads();
    int e = blockIdx.x * blockDim.x + threadIdx.x;
    if (e < EE) {
        atomicAdd(&h[et[e]], 1);
        atomicAdd(&g_cnt[dst[e]], 1);
    }
    __syncthreads();
    if (threadIdx.x < NREL) atomicAdd(&g_hist[threadIdx.x], h[threadIdx.x]);
}

// ---------------- K3: local scan + counting-sort scatter (warp-aggregated) --------
__global__ void k_scatter(const int* __restrict__ nid, const int* __restrict__ src,
                          const int* __restrict__ dst, const int* __restrict__ et,
                          const float* __restrict__ norm) {
    __shared__ int s_off[NREL];
    if (threadIdx.x == 0) {
        int acc = 0;
        for (int r = 0; r < NREL; r++) {
            s_off[r] = acc;
            if (blockIdx.x == 0) g_offpad[r] = acc;
            acc += ((g_hist[r] + TILE_M - 1) / TILE_M) * TILE_M;
        }
        if (blockIdx.x == 0) g_offpad[NREL] = acc;
    }
    __syncthreads();
    int e = blockIdx.x * blockDim.x + threadIdx.x;
    if (e >= EE) return;  // EE % 256 == 0: warps stay converged
    int t = et[e];
    int lane = threadIdx.x & 31;
    unsigned mask = __match_any_sync(0xffffffffu, t);
    int leader = __ffs(mask) - 1;
    int base;
    if (lane == leader) base = atomicAdd(&g_relcnt[t], __popc(mask));
    base = __shfl_sync(mask, base, leader);
    int pos = s_off[t] + base + __popc(mask & ((1u << lane) - 1u));
    g_srcrow[pos] = nid[src[e]];
    g_dstn[pos]   = dst[e];
    g_normv[pos]  = norm[e];
}

// ---------------- K4: grouped GEMM (tf32 mma, 64x64 warp tiles) -------------------
// Block = 256 edges x 128 out-cols, 8 warps as 4(M) x 2(N), warp tile 64x64.
// 4-stage cp.async pipeline; stage = A(256x32, 32KB) + B(32x128, 16KB).
// Epilogue: norm-scale, stage 256x128 fp32 in smem, red.global.add.v4 to out[dst].
__global__ void __launch_bounds__(256) k_gemm(const float* __restrict__ emb,
                                              float* __restrict__ out) {
    extern __shared__ __align__(1024) float smemf[];
    __shared__ int   sdst[TILE_M];
    __shared__ int   ssrc[TILE_M];
    __shared__ float snorm[TILE_M];

    int row0 = blockIdx.x * TILE_M;
    if (row0 >= g_offpad[NREL]) return;
    int r = 0;
#pragma unroll
    for (int i = 1; i < NREL; i++) r += (g_offpad[i] <= row0) ? 1 : 0;

    int tid  = threadIdx.x;
    int wid  = tid >> 5;
    int lane = tid & 31;

    uint32_t sb = (uint32_t)__cvta_generic_to_shared(smemf);

    sdst[tid]  = g_dstn[row0 + tid];
    ssrc[tid]  = g_srcrow[row0 + tid];
    snorm[tid] = g_normv[row0 + tid];
    __syncthreads();

    const float* Wr = g_W + (size_t)r * (DD * DD) + blockIdx.y * 128;

    // stage s covers K columns [s*32, s*32+32), buffer buf
    auto loadstage = [&](int s, int buf) {
        uint32_t bb = sb + (uint32_t)buf * STAGE_BYTES;
#pragma unroll
        for (int v = tid; v < 2048; v += 256) {       // A: 256 rows x 8 float4
            int row = v >> 3;
            int c4  = (v & 7) << 2;
            const float* g = emb + (size_t)ssrc[row] * DD + s * 32 + c4;
            uint32_t a = bb + row * 128u + ((c4 ^ ((row & 7) << 2)) << 2);
            cp16(a, g);
        }
#pragma unroll
        for (int v = tid; v < 1024; v += 256) {       // B: 32 k-rows x 32 float4
            int k  = v >> 5;
            int j4 = (v & 31) << 2;
            const float* g = Wr + (size_t)(s * 32 + k) * DD + j4;
            uint32_t a = bb + 32768u + k * 512u + ((j4 ^ ((k & 3) << 3)) << 2);
            cp16(a, g);
        }
        cp_commit();
    };

    int wm = (wid & 3) * 64;    // 4 warps over M (64 rows each)
    int wn = (wid >> 2) * 64;   // 2 warps over N (64 cols each)
    int qr = lane >> 2, qc = lane & 3;

    float acc[4][8][4];
#pragma unroll
    for (int mt = 0; mt < 4; mt++)
#pragma unroll
        for (int nt = 0; nt < 8; nt++)
#pragma unroll
            for (int k = 0; k < 4; k++) acc[mt][nt][k] = 0.0f;

    loadstage(0, 0);
    loadstage(1, 1);
    loadstage(2, 2);

#pragma unroll 1
    for (int it = 0; it < 8; it++) {
        asm volatile("cp.async.wait_group 2;\n" ::: "memory");
        __syncthreads();
        if (it + 3 < 8) loadstage(it + 3, (it + 3) & 3);
        else            cp_commit();   // empty group keeps the count aligned

        const float* cA = smemf + (it & 3) * (STAGE_BYTES / 4);
        const float* cB = cA + 8192;
#pragma unroll
        for (int ks = 0; ks < 32; ks += 8) {
            unsigned af[4][4];
#pragma unroll
            for (int mt = 0; mt < 4; mt++) {
                int rlo = wm + mt * 16 + qr;
                int rhi = rlo + 8;
                int sw  = (rlo & 7) << 2;   // rhi & 7 == rlo & 7
                af[mt][0] = __float_as_uint(cA[rlo * 32 + ((ks + qc)     ^ sw)]);
                af[mt][1] = __float_as_uint(cA[rhi * 32 + ((ks + qc)     ^ sw)]);
                af[mt][2] = __float_as_uint(cA[rlo * 32 + ((ks + 4 + qc) ^ sw)]);
                af[mt][3] = __float_as_uint(cA[rhi * 32 + ((ks + 4 + qc) ^ sw)]);
            }
            int swb = qc << 3;
#pragma unroll
            for (int nt = 0; nt < 8; nt++) {
                int col = wn + nt * 8 + qr;
                unsigned b0 = __float_as_uint(cB[(ks + qc)     * 128 + (col ^ swb)]);
                unsigned b1 = __float_as_uint(cB[(ks + 4 + qc) * 128 + (col ^ swb)]);
                mma_tf32(acc[0][nt], af[0], b0, b1);
                mma_tf32(acc[1][nt], af[1], b0, b1);
                mma_tf32(acc[2][nt], af[2], b0, b1);
                mma_tf32(acc[3][nt], af[3], b0, b1);
            }
        }
        __syncthreads();
    }

    // --- epilogue: scale by norm, stage 256x128 tile (swizzled), vector reds ----
    float* sT = smemf;   // 256*128 floats = 128KB (fits in 192KB)
#pragma unroll
    for (int mt = 0; mt < 4; mt++) {
        int rlo = wm + mt * 16 + qr;
        int rhi = rlo + 8;
        float n0 = snorm[rlo];
        float n1 = snorm[rhi];
        int sw = (rlo & 7) << 2;
#pragma unroll
        for (int nt = 0; nt < 8; nt++) {
            int col = wn + nt * 8 + qc * 2;
            float2 lo = make_float2(acc[mt][nt][0] * n0, acc[mt][nt][1] * n0);
            float2 hi = make_float2(acc[mt][nt][2] * n1, acc[mt][nt][3] * n1);
            *reinterpret_cast<float2*>(&sT[rlo * 128 + (col ^ sw)]) = lo;
            *reinterpret_cast<float2*>(&sT[rhi * 128 + (col ^ sw)]) = hi;
        }
    }
    __syncthreads();

    int colbase = blockIdx.y * 128;
#pragma unroll 1
    for (int v = tid; v < 8192; v += 256) {
        int row = v >> 5;
        int c4  = (v & 31) << 2;
        int d = sdst[row];
        if (d < 0) continue;
        int sw = (row & 7) << 2;
        float4 val = *reinterpret_cast<float4*>(&sT[row * 128 + (c4 ^ sw)]);
        red4(out + (size_t)d * DD + colbase + c4, val.x, val.y, val.z, val.w);
    }
}

// ---------------- K5: mean + bias ----------------
__global__ void k_final(float* __restrict__ out, const float* __restrict__ hbias) {
    int i = blockIdx.x * blockDim.x + threadIdx.x;
    if (i >= NNODES * DD) return;
    int n = i >> 8;
    int c = i & 255;
    float cnt = (float)g_cnt[n];
    float v = out[i];
    v = (cnt > 0.0f) ? v / cnt : 0.0f;
    out[i] = v + hbias[c];
}

// ---------------- launch ----------------
extern "C" void kernel_launch(void* const* d_in, const int* in_sizes, int n_in,
                              void* d_out, int out_size) {
    const int*   node_ids = (const int*)  d_in[0];
    const int*   src      = (const int*)  d_in[1];
    const int*   dst      = (const int*)  d_in[2];
    const int*   etypes   = (const int*)  d_in[3];
    const float* norm     = (const float*)d_in[4];
    const float* emb      = (const float*)d_in[5];
    const float* basis    = (const float*)d_in[6];
    const float* wcomp    = (const float*)d_in[7];
    const float* hbias    = (const float*)d_in[8];
    float* out = (float*)d_out;

    static bool attr_set = false;
    if (!attr_set) {
        cudaFuncSetAttribute(k_gemm, cudaFuncAttributeMaxDynamicSharedMemorySize,
                             SMEM_BYTES);
        attr_set = true;
    }

    k_pre<<<8192, 256>>>(out, basis, wcomp);                                 // 1
    k_hist<<<(EE + 255) / 256, 256>>>(etypes, dst);                          // 2
    k_scatter<<<(EE + 255) / 256, 256>>>(node_ids, src, dst, etypes, norm);  // 3
    dim3 g(NTILES, 2);
    k_gemm<<<g, 256, SMEM_BYTES>>>(emb, out);                                // 4 (profiled)
    k_final<<<(NNODES * DD + 255) / 256, 256>>>(out, hbias);                 // 5
}